// round 1
// baseline (speedup 1.0000x reference)
#include <cuda_runtime.h>
#include <math.h>

#define NB 8
#define NO 128
#define NR 8
#define NH 48
#define NHW 2304
#define NX 64

// ---- output layout (concatenated flattened outputs, float32) ----
#define OFF_ATTN 0
#define OFF_Q    147456
#define OFF_PR   294912
#define OFF_A    294920
#define OFF_OFF  442376
#define OFF_TH   442384
#define OFF_Z    737296

// ---- device scratch (static, no runtime allocation) ----
__device__ float d_rot17[NR * NO * 17 * 17];
__device__ float d_rot33[NR * NO * 33 * 33];
__device__ float d_xout[NB * NO * NR * NHW];     // [b][c][r][hw]
__device__ float d_attn1[NB * NR * NHW];
__device__ float d_attn0[NB * 4 * NHW];
__device__ float d_z1[NB * 4 * NR * NHW];        // [b][l][r][hw]
__device__ float d_z0[NB * 4 * 4 * NHW];
__device__ float d_stats[NB * 4];                // m1, s1, m2, s2

__constant__ float c_offs[8] = {
    0.0f, 0.7853981633974483f, 1.5707963267948966f, 2.356194490192345f,
    3.141592653589793f, -2.356194490192345f, -1.5707963267948966f,
    -0.7853981633974483f};

#define LOG_SIGMA   1.1447298858494002f   // log(pi), f32
#define HALF_LOG2PI 0.9189385332046727f   // 0.5*log(2*pi), f32
#define PI_F        3.14159265358979323846f

// ============================================================
// K1: rotate kernels (bilinear grid_sample semantics, zero pad)
// ============================================================
template <int K>
__global__ void rotate_kern(const float* __restrict__ w) {
    constexpr int KK = K * K;
    float* out = (K == 17) ? d_rot17 : d_rot33;
    int idx = blockIdx.x * blockDim.x + threadIdx.x;
    if (idx >= NR * NO * KK) return;
    int j = idx % K;
    int t = idx / K;
    int i = t % K; t /= K;
    int o = t % NO;
    int r = t / NO;

    float theta = 0.7853981633974483f * (float)r;  // (2*pi/8)*r in f32
    float c = cosf(theta), s = sinf(theta);
    float gy = (2.0f * (float)i + 1.0f) / (float)K - 1.0f;
    float gx = (2.0f * (float)j + 1.0f) / (float)K - 1.0f;
    float sx = c * gx - s * gy;
    float sy = s * gx + c * gy;
    float fx = ((sx + 1.0f) * (float)K - 1.0f) * 0.5f;
    float fy = ((sy + 1.0f) * (float)K - 1.0f) * 0.5f;
    int x0 = (int)floorf(fx);
    int y0 = (int)floorf(fy);
    float wx1 = fx - (float)x0;
    float wy1 = fy - (float)y0;
    const float* wo = w + o * KK;

    auto g = [&](int y, int x) -> float {
        if (y < 0 || y >= K || x < 0 || x >= K) return 0.0f;
        return wo[y * K + x];
    };
    float v = g(y0, x0) * (1.0f - wy1) * (1.0f - wx1)
            + g(y0, x0 + 1) * (1.0f - wy1) * wx1
            + g(y0 + 1, x0) * wy1 * (1.0f - wx1)
            + g(y0 + 1, x0 + 1) * wy1 * wx1;
    out[idx] = v;
}

// ============================================================
// K2: group conv + bias + lrelu + alpha-combine into d_xout
//   block: fixed (b, r), 4 output channels, full 48x48 spatial
//   thread: 8 rows x 1 col strip  (288 threads = 6 row-tiles x 48 cols)
// ============================================================
template <int K, int PAD, bool FIRST>
__global__ __launch_bounds__(288) void conv_group(
    const float* __restrict__ x, const float* __restrict__ bias,
    const float* __restrict__ kw, const float* __restrict__ gk) {
    constexpr int XD = NX + 2 * PAD;
    constexpr int XS = XD + 1;
    constexpr int KK = K * K;
    const float* rot = (K == 17) ? d_rot17 : d_rot33;

    __shared__ float xs[XD * XS];
    __shared__ float ws[4 * KK];

    int tid = threadIdx.x;
    int b = blockIdx.y >> 3;
    int r = blockIdx.y & 7;
    int o0 = blockIdx.x * 4;

    const float* xb = x + b * NX * NX;
    for (int idx = tid; idx < XD * XD; idx += 288) {
        int row = idx / XD, col = idx - row * XD;
        int gr = row - PAD, gc = col - PAD;
        float v = 0.0f;
        if (gr >= 0 && gr < NX && gc >= 0 && gc < NX) v = xb[gr * NX + gc];
        xs[row * XS + col] = v;
    }
    const float* rbase = rot + (r * NO + o0) * KK;
    for (int idx = tid; idx < 4 * KK; idx += 288) ws[idx] = rbase[idx];
    __syncthreads();

    int tc = tid % 48;
    int tr0 = (tid / 48) * 8;

    float acc[4][8];
#pragma unroll
    for (int o = 0; o < 4; ++o)
#pragma unroll
        for (int e = 0; e < 8; ++e) acc[o][e] = 0.0f;

#pragma unroll 1
    for (int ky = 0; ky < K; ++ky) {
        const float* xp = xs + (tr0 + ky) * XS + tc;
        const float* wp = ws + ky * K;
        for (int kx = 0; kx < K; ++kx) {
            float xv[8];
#pragma unroll
            for (int dr = 0; dr < 8; ++dr) xv[dr] = xp[dr * XS + kx];
#pragma unroll
            for (int o = 0; o < 4; ++o) {
                float wv = wp[o * KK + kx];
#pragma unroll
                for (int dr = 0; dr < 8; ++dr)
                    acc[o][dr] = fmaf(wv, xv[dr], acc[o][dr]);
            }
        }
    }

    // gumbel-softmax alpha over kernel sizes
    float l0 = (kw[0] + gk[0]) / 10.0f;
    float l1 = (kw[1] + gk[1]) / 10.0f;
    float mm = fmaxf(l0, l1);
    float e0 = expf(l0 - mm), e1 = expf(l1 - mm);
    float alpha = (FIRST ? e0 : e1) / (e0 + e1);

#pragma unroll
    for (int o = 0; o < 4; ++o) {
        float bo = bias[o0 + o];
        float* op = d_xout + (((b * NO + o0 + o) * NR + r) * NHW) + tr0 * 48 + tc;
#pragma unroll
        for (int dr = 0; dr < 8; ++dr) {
            float v = acc[o][dr] + bo;
            v = (v >= 0.0f) ? v : 0.01f * v;
            v *= alpha;
            if (FIRST) op[dr * 48] = v;
            else       op[dr * 48] += v;
        }
    }
}

// ============================================================
// K3: fused conv2(128x128) + lrelu + conva(1) + convz(4) heads
//   block: fixed (b, r, spatial row h); 256 thr = 16 o-grp x 16 n-grp
//   thread: 8 o (stride-16 interleave) x 3 spatial
// ============================================================
template <int BRANCH>
__global__ __launch_bounds__(256) void gemm_attnz(
    const float* __restrict__ w2, const float* __restrict__ b2,
    const float* __restrict__ wa, const float* __restrict__ ba,
    const float* __restrict__ wz, const float* __restrict__ bz) {
    constexpr int RCOUNT = BRANCH ? 8 : 4;
    constexpr int RSTEP = BRANCH ? 1 : 2;
    float* attn_out = BRANCH ? d_attn1 : d_attn0;
    float* z_out = BRANCH ? d_z1 : d_z0;

    __shared__ float ws[128 * 33];   // [o][cc], padded stride 33
    __shared__ float xt[128 * 48];   // [c][n]

    int tid = threadIdx.x;
    int to = tid & 15;
    int tn = tid >> 4;
    int h = blockIdx.x;
    int brs = blockIdx.y;
    int b = brs / RCOUNT;
    int rsub = brs - b * RCOUNT;
    int r = rsub * RSTEP;

    const float* xb = d_xout + ((b * NO) * NR + r) * NHW + h * 48;
    for (int idx = tid; idx < 6144; idx += 256) {
        int c = idx / 48, n = idx - c * 48;
        xt[idx] = xb[c * (NR * NHW) + n];
    }

    float acc[8][3];
#pragma unroll
    for (int oo = 0; oo < 8; ++oo)
#pragma unroll
        for (int j = 0; j < 3; ++j) acc[oo][j] = 0.0f;

    for (int kc = 0; kc < 4; ++kc) {
        __syncthreads();
        for (int idx = tid; idx < 4096; idx += 256) {
            int o = idx >> 5, cc = idx & 31;
            ws[o * 33 + cc] = w2[o * 128 + kc * 32 + cc];
        }
        __syncthreads();
#pragma unroll 4
        for (int cc = 0; cc < 32; ++cc) {
            int k = kc * 32 + cc;
            float xv[3];
#pragma unroll
            for (int j = 0; j < 3; ++j) xv[j] = xt[k * 48 + tn * 3 + j];
#pragma unroll
            for (int oo = 0; oo < 8; ++oo) {
                float wv = ws[(oo * 16 + to) * 33 + cc];
                acc[oo][0] = fmaf(wv, xv[0], acc[oo][0]);
                acc[oo][1] = fmaf(wv, xv[1], acc[oo][1]);
                acc[oo][2] = fmaf(wv, xv[2], acc[oo][2]);
            }
        }
    }

    // epilogue: h = lrelu(acc + b2[o]); heads reduce over o
    float pa[3] = {0.f, 0.f, 0.f};
    float pz[4][3];
#pragma unroll
    for (int l = 0; l < 4; ++l)
#pragma unroll
        for (int j = 0; j < 3; ++j) pz[l][j] = 0.0f;

#pragma unroll
    for (int oo = 0; oo < 8; ++oo) {
        int o = oo * 16 + to;
        float bb = b2[o];
        float wav = wa[o];
        float w0 = wz[o], w1 = wz[128 + o], w2v = wz[256 + o], w3 = wz[384 + o];
#pragma unroll
        for (int j = 0; j < 3; ++j) {
            float hv = acc[oo][j] + bb;
            hv = (hv >= 0.0f) ? hv : 0.01f * hv;
            pa[j] = fmaf(wav, hv, pa[j]);
            pz[0][j] = fmaf(w0, hv, pz[0][j]);
            pz[1][j] = fmaf(w1, hv, pz[1][j]);
            pz[2][j] = fmaf(w2v, hv, pz[2][j]);
            pz[3][j] = fmaf(w3, hv, pz[3][j]);
        }
    }

    // reduce across the 16 o-groups (lanes differing in bits 0..3)
#pragma unroll
    for (int m = 8; m >= 1; m >>= 1) {
#pragma unroll
        for (int j = 0; j < 3; ++j) {
            pa[j] += __shfl_xor_sync(0xffffffffu, pa[j], m);
#pragma unroll
            for (int l = 0; l < 4; ++l)
                pz[l][j] += __shfl_xor_sync(0xffffffffu, pz[l][j], m);
        }
    }

    if (to == 0) {
        int nbase = h * 48 + tn * 3;
#pragma unroll
        for (int j = 0; j < 3; ++j)
            attn_out[(b * RCOUNT + rsub) * NHW + nbase + j] = pa[j] + ba[0];
#pragma unroll
        for (int l = 0; l < 4; ++l)
#pragma unroll
            for (int j = 0; j < 3; ++j)
                z_out[((b * 4 + l) * RCOUNT + rsub) * NHW + nbase + j] =
                    pz[l][j] + bz[l];
    }
}

// ============================================================
// K4: scatter combine (betas) + p_r; writes attn, z, theta,
//     p_r, offsets directly into d_out
// ============================================================
__global__ void combine_kern(const float* __restrict__ rw,
                             const float* __restrict__ gr,
                             float* __restrict__ out) {
    int idx = blockIdx.x * blockDim.x + threadIdx.x;
    if (idx >= NB * NR * NHW) return;

    float l0 = (rw[0] + gr[0]) / 10.0f;
    float l1 = (rw[1] + gr[1]) / 10.0f;
    float mm = fmaxf(l0, l1);
    float e0 = expf(l0 - mm), e1 = expf(l1 - mm);
    float inv = 1.0f / (e0 + e1);
    float b0 = e0 * inv, b1 = e1 * inv;

    int b = idx / (NR * NHW);
    int rem = idx - b * (NR * NHW);
    int r = rem / NHW;
    int hw = rem - r * NHW;
    float off = c_offs[r];
    float t = off / PI_F;
    float pr = -0.5f * t * t - LOG_SIGMA - HALF_LOG2PI;

    float a = b1 * d_attn1[(b * NR + r) * NHW + hw];
    bool even = ((r & 1) == 0);
    if (even) a += b0 * d_attn0[(b * 4 + (r >> 1)) * NHW + hw];
    a += pr;
    out[OFF_ATTN + idx] = a;

    float zv[4];
#pragma unroll
    for (int l = 0; l < 4; ++l) {
        float z = b1 * d_z1[((b * 4 + l) * NR + r) * NHW + hw];
        if (even) z += b0 * d_z0[((b * 4 + l) * 4 + (r >> 1)) * NHW + hw];
        zv[l] = z;
        out[OFF_Z + ((b * 4 + l) * NR + r) * NHW + hw] = z;
    }
    out[OFF_TH + ((b * 2 + 0) * NR + r) * NHW + hw] = zv[0] + off;
    out[OFF_TH + ((b * 2 + 1) * NR + r) * NHW + hw] = zv[1];

    if (idx < 8) {
        float o2 = c_offs[idx];
        float t2 = o2 / PI_F;
        out[OFF_PR + idx] = -0.5f * t2 * t2 - LOG_SIGMA - HALF_LOG2PI;
        out[OFF_OFF + idx] = o2;
    }
}

// ============================================================
// K5: per-batch softmax stats (max / sumexp, two distributions)
// ============================================================
__global__ void stats_kern(const float* __restrict__ out,
                           const float* __restrict__ g) {
    __shared__ float sm[256];
    int b = blockIdx.x, tid = threadIdx.x;
    const float* a = out + OFF_ATTN + b * (NR * NHW);
    const float* gb = g + b * (NR * NHW);

    float m1 = -1e30f, m2 = -1e30f;
    for (int i = tid; i < NR * NHW; i += 256) {
        float v = a[i];
        m1 = fmaxf(m1, v);
        m2 = fmaxf(m2, v + gb[i]);
    }
    sm[tid] = m1; __syncthreads();
    for (int s = 128; s > 0; s >>= 1) {
        if (tid < s) sm[tid] = fmaxf(sm[tid], sm[tid + s]);
        __syncthreads();
    }
    m1 = sm[0]; __syncthreads();
    sm[tid] = m2; __syncthreads();
    for (int s = 128; s > 0; s >>= 1) {
        if (tid < s) sm[tid] = fmaxf(sm[tid], sm[tid + s]);
        __syncthreads();
    }
    m2 = sm[0]; __syncthreads();

    float s1 = 0.0f, s2 = 0.0f;
    for (int i = tid; i < NR * NHW; i += 256) {
        float v = a[i];
        s1 += expf(v - m1);
        s2 += expf(v + gb[i] - m2);
    }
    sm[tid] = s1; __syncthreads();
    for (int s = 128; s > 0; s >>= 1) {
        if (tid < s) sm[tid] += sm[tid + s];
        __syncthreads();
    }
    s1 = sm[0]; __syncthreads();
    sm[tid] = s2; __syncthreads();
    for (int s = 128; s > 0; s >>= 1) {
        if (tid < s) sm[tid] += sm[tid + s];
        __syncthreads();
    }
    s2 = sm[0];

    if (tid == 0) {
        d_stats[b * 4 + 0] = m1;
        d_stats[b * 4 + 1] = s1;
        d_stats[b * 4 + 2] = m2;
        d_stats[b * 4 + 3] = s2;
    }
}

// ============================================================
// K6: q_t_r (log_softmax) + a_sampled (gumbel softmax)
// ============================================================
__global__ void final_kern(const float* __restrict__ g,
                           float* __restrict__ out) {
    int idx = blockIdx.x * blockDim.x + threadIdx.x;
    if (idx >= NB * NR * NHW) return;
    int b = idx / (NR * NHW);
    float v = out[OFF_ATTN + idx];
    out[OFF_Q + idx] = (v - d_stats[b * 4 + 0]) - logf(d_stats[b * 4 + 1]);
    out[OFF_A + idx] =
        expf(v + g[idx] - d_stats[b * 4 + 2]) / d_stats[b * 4 + 3];
}

// ============================================================
extern "C" void kernel_launch(void* const* d_in, const int* in_sizes, int n_in,
                              void* d_out, int out_size) {
    const float* x   = (const float*)d_in[0];
    const float* ksw = (const float*)d_in[1];
    const float* rdw = (const float*)d_in[2];
    const float* w17 = (const float*)d_in[3];
    const float* b17 = (const float*)d_in[4];
    const float* w33 = (const float*)d_in[5];
    const float* b33 = (const float*)d_in[6];
    const float* w2  = (const float*)d_in[7];
    const float* b2  = (const float*)d_in[8];
    const float* wa  = (const float*)d_in[9];
    const float* ba  = (const float*)d_in[10];
    const float* wz  = (const float*)d_in[11];
    const float* bz  = (const float*)d_in[12];
    const float* gk  = (const float*)d_in[13];
    const float* gr  = (const float*)d_in[14];
    const float* ga  = (const float*)d_in[15];
    float* out = (float*)d_out;

    rotate_kern<17><<<(NR * NO * 289 + 255) / 256, 256>>>(w17);
    rotate_kern<33><<<(NR * NO * 1089 + 255) / 256, 256>>>(w33);

    conv_group<17, 0, true ><<<dim3(32, 64), 288>>>(x, b17, ksw, gk);
    conv_group<33, 8, false><<<dim3(32, 64), 288>>>(x, b33, ksw, gk);

    gemm_attnz<1><<<dim3(48, 64), 256>>>(w2 + 16384, b2 + 128, wa + 128,
                                         ba + 1, wz + 512, bz + 4);
    gemm_attnz<0><<<dim3(48, 32), 256>>>(w2, b2, wa, ba, wz, bz);

    combine_kern<<<(NB * NR * NHW + 255) / 256, 256>>>(rdw, gr, out);
    stats_kern<<<NB, 256>>>(out, ga);
    final_kern<<<(NB * NR * NHW + 255) / 256, 256>>>(ga, out);
}